// round 16
// baseline (speedup 1.0000x reference)
#include <cuda_runtime.h>
#include <cuda_fp16.h>
#include <math.h>
#include <stdint.h>

#define N_NODES 50000
#define N_EDGES 500000
#define DIM 128
#define BN_EPS 1e-5f

#define BLK_M 64
#define AS_U32 68        // A smem row stride in uint32 (64 half2 + 4 pad) — bank-clean
#define WS_U32 68        // W smem row stride in uint32
#define CS_STRIDE 136    // fp32 Cs stride (gemm_bias)
#define CS_U32 68        // fp16 Cs stride in uint32 (edge kernel)
#define SMEM_G_BYTES ((BLK_M * AS_U32 + 128 * WS_U32) * 4)   // 52224 B

// ---------------- scratch (device globals; no allocations allowed) ----------
__device__ float  g_AX[N_NODES * DIM];            // fp32 (feeds H path directly)
__device__ __half g_BX[N_NODES * DIM];            // fp16 gather arrays
__device__ __half g_DX[N_NODES * DIM];
__device__ __half g_EX[N_NODES * DIM];
__device__ __half g_num[N_NODES * DIM];           // fp16 atomic reduction targets
__device__ __half g_den[N_NODES * DIM];
__device__ __half g_E16[(size_t)N_EDGES * DIM];   // fp16 Epre intermediate
__device__ __half g_Wt[5 * DIM * DIM];            // fp16 n-major weights: A,B,D,E,C
__device__ float  g_hsum[DIM];
__device__ float  g_hsq[DIM];
__device__ float  g_esum[DIM];
__device__ float  g_esq[DIM];

// ---------------- helpers ----------------------------------------------------
__device__ __forceinline__ void red_add_h4(__half* addr, uint32_t h01, uint32_t h23) {
    asm volatile("red.global.add.noftz.v2.f16x2 [%0], {%1, %2};"
                 :: "l"(addr), "r"(h01), "r"(h23)
                 : "memory");
}

__device__ __forceinline__ void mma_f16(float c[4],
                                        uint32_t a0, uint32_t a1, uint32_t a2, uint32_t a3,
                                        uint32_t b0, uint32_t b1) {
    asm volatile("mma.sync.aligned.m16n8k16.row.col.f32.f16.f16.f32 "
                 "{%0,%1,%2,%3},{%4,%5,%6,%7},{%8,%9},{%0,%1,%2,%3};"
                 : "+f"(c[0]), "+f"(c[1]), "+f"(c[2]), "+f"(c[3])
                 : "r"(a0), "r"(a1), "r"(a2), "r"(a3), "r"(b0), "r"(b1));
}

__device__ __forceinline__ uint32_t h2bits(__half2 h) {
    return *reinterpret_cast<uint32_t*>(&h);
}

// ---------------- Wt prep: W[k][n] fp32 -> Wt[n][k] fp16 (n-major) --------------
__global__ void wt_prep(const float* __restrict__ W0, const float* __restrict__ W1,
                        const float* __restrict__ W2, const float* __restrict__ W3,
                        const float* __restrict__ W4, __half2* __restrict__ Wt) {
    int gid = blockIdx.x * 256 + threadIdx.x;     // 5*128*64 = 40960
    if (gid >= 5 * 128 * 64) return;
    int k2 = gid & 63;
    int n  = (gid >> 6) & 127;
    int w  = gid >> 13;
    const float* W = (w == 0) ? W0 : (w == 1) ? W1 : (w == 2) ? W2 : (w == 3) ? W3 : W4;
    Wt[gid] = __floats2half2_rn(W[(2 * k2) * 128 + n], W[(2 * k2 + 1) * 128 + n]);
}

// ================================================================================
// FP16 tensor-core GEMM core (R15-proven): 64x128 tile, 256 threads, 8 warps
// (2 row-groups x 4 col-groups; warp tile 32x32, acc[2][4][4] fp32). m16n8k16.
// ================================================================================
template <bool STREAM_A>
__device__ __forceinline__ void gemm_f16(const float* __restrict__ A,
                                         const __half* __restrict__ Wt,
                                         int rowBase, int M, uint32_t* smemu,
                                         float acc[2][4][4], int tid) {
    int lane = tid & 31, wid = tid >> 5;
    int wr = wid & 1, wc = wid >> 1;
    uint32_t* Asu = smemu;
    uint32_t* Wsu = smemu + BLK_M * AS_U32;
    const uint32_t* Wtu = (const uint32_t*)Wt;

    #pragma unroll
    for (int h = 0; h < 2; h++)
        #pragma unroll
        for (int t = 0; t < 4; t++)
            #pragma unroll
            for (int j = 0; j < 4; j++) acc[h][t][j] = 0.f;

    #pragma unroll
    for (int u = 0; u < 8; u++) {
        int idx = tid + u * 256;
        int r  = idx >> 5;
        int c4 = idx & 31;
        int gr = min(rowBase + r, M - 1);
        const float4* ap = &((const float4*)A)[(long)gr * 32 + c4];
        float4 v = STREAM_A ? __ldcs(ap) : *ap;
        uint2 st;
        st.x = h2bits(__floats2half2_rn(v.x, v.y));
        st.y = h2bits(__floats2half2_rn(v.z, v.w));
        *(uint2*)&Asu[r * AS_U32 + c4 * 2] = st;
    }
    #pragma unroll
    for (int u = 0; u < 8; u++) {
        int idx = tid + u * 256;
        int n  = idx >> 4;
        int q4 = idx & 15;
        uint4 v = *(const uint4*)&Wtu[n * 64 + q4 * 4];
        *(uint4*)&Wsu[n * WS_U32 + q4 * 4] = v;
    }
    __syncthreads();

    int akl = lane & 3;
    int aro = lane >> 2;

    #pragma unroll
    for (int ks = 0; ks < 8; ks++) {
        int kb = ks * 8;
        uint32_t a[2][4];
        #pragma unroll
        for (int h = 0; h < 2; h++) {
            int r = wr * 32 + h * 16 + aro;
            a[h][0] = Asu[r * AS_U32 + kb + akl];
            a[h][1] = Asu[(r + 8) * AS_U32 + kb + akl];
            a[h][2] = Asu[r * AS_U32 + kb + 4 + akl];
            a[h][3] = Asu[(r + 8) * AS_U32 + kb + 4 + akl];
        }
        #pragma unroll
        for (int t = 0; t < 4; t++) {
            int n = wc * 32 + t * 8 + aro;
            uint32_t b0 = Wsu[n * WS_U32 + kb + akl];
            uint32_t b1 = Wsu[n * WS_U32 + kb + 4 + akl];
            mma_f16(acc[0][t], a[0][0], a[0][1], a[0][2], a[0][3], b0, b1);
            mma_f16(acc[1][t], a[1][0], a[1][1], a[1][2], a[1][3], b0, b1);
        }
    }
    __syncthreads();
}

// fp32 Cs store (gemm_bias; protects AX precision)
__device__ __forceinline__ void store_f32(float* Cs, float acc[2][4][4], int h32, int tid) {
    int lane = tid & 31, wid = tid >> 5;
    int wr = wid & 1, wc = wid >> 1;
    if (wr == h32) {
        #pragma unroll
        for (int h = 0; h < 2; h++) {
            int lr = h * 16 + (lane >> 2);
            #pragma unroll
            for (int t = 0; t < 4; t++) {
                int c = wc * 32 + t * 8 + 2 * (lane & 3);
                *(float2*)&Cs[lr * CS_STRIDE + c]       = make_float2(acc[h][t][0], acc[h][t][1]);
                *(float2*)&Cs[(lr + 8) * CS_STRIDE + c] = make_float2(acc[h][t][2], acc[h][t][3]);
            }
        }
    }
}

// fp16 Cs store (edge kernel; halves transpose bytes)
__device__ __forceinline__ void store_h16(uint32_t* Cs, float acc[2][4][4], int h32, int tid) {
    int lane = tid & 31, wid = tid >> 5;
    int wr = wid & 1, wc = wid >> 1;
    if (wr == h32) {
        #pragma unroll
        for (int h = 0; h < 2; h++) {
            int lr = h * 16 + (lane >> 2);
            #pragma unroll
            for (int t = 0; t < 4; t++) {
                int ch = wc * 16 + t * 4 + (lane & 3);   // half2 column index
                Cs[lr * CS_U32 + ch]       = h2bits(__floats2half2_rn(acc[h][t][0], acc[h][t][1]));
                Cs[(lr + 8) * CS_U32 + ch] = h2bits(__floats2half2_rn(acc[h][t][2], acc[h][t][3]));
            }
        }
    }
}

// ---------------- zero scratch (num/den are half: 800k uint4 each) --------------
__global__ void zero_scratch(uint4* num4, uint4* den4,
                             float* hsum, float* hsq, float* esum, float* esq) {
    int i = blockIdx.x * blockDim.x + threadIdx.x;   // exactly 800,000 threads
    uint4 z = make_uint4(0u, 0u, 0u, 0u);
    num4[i] = z;
    den4[i] = z;
    if (i < DIM) { hsum[i] = 0.f; hsq[i] = 0.f; esum[i] = 0.f; esq[i] = 0.f; }
}

// ---------------- fused node GEMMs (fp16 MMA; AX fp32, B/D/E fp16 out) ----------
__global__ __launch_bounds__(256, 3)
void gemm_bias(const float* __restrict__ A, const __half* __restrict__ Wt,
               const float* __restrict__ b0p, float*  __restrict__ o0,
               const float* __restrict__ b1p, __half* __restrict__ o1,
               const float* __restrict__ b2p, __half* __restrict__ o2,
               const float* __restrict__ b3p, __half* __restrict__ o3,
               int M) {
    extern __shared__ uint32_t smemu[];
    float* Cs = (float*)smemu;   // alias after GEMM (32 x 136 fp32 = 17408 B fits in As)

    const float* bias;
    float*  outf = 0;
    __half* outh = 0;
    switch (blockIdx.y) {
        case 0:  bias = b0p; outf = o0; break;
        case 1:  bias = b1p; outh = o1; break;
        case 2:  bias = b2p; outh = o2; break;
        default: bias = b3p; outh = o3; break;
    }
    const __half* Wtw = Wt + (long)blockIdx.y * DIM * DIM;
    int tid = threadIdx.x;
    int rowBase = blockIdx.x * BLK_M;

    float acc[2][4][4];
    gemm_f16<false>(A, Wtw, rowBase, M, smemu, acc, tid);

    #pragma unroll
    for (int h32 = 0; h32 < 2; h32++) {
        store_f32(Cs, acc, h32, tid);
        __syncthreads();
        int r = tid >> 3, q = tid & 7;
        int grow = rowBase + h32 * 32 + r;
        if (grow < M) {
            #pragma unroll
            for (int cb = 0; cb < 4; cb++) {
                int c = q * 16 + cb * 4;
                float4 v = *(float4*)&Cs[r * CS_STRIDE + c];
                float4 bb = __ldg((const float4*)&bias[c]);
                v.x += bb.x; v.y += bb.y; v.z += bb.z; v.w += bb.w;
                if (blockIdx.y == 0) {
                    *(float4*)&outf[(long)grow * 128 + c] = v;
                } else {
                    uint2 u;
                    u.x = h2bits(__floats2half2_rn(v.x, v.y));
                    u.y = h2bits(__floats2half2_rn(v.z, v.w));
                    *(uint2*)&outh[(long)grow * 128 + c] = u;
                }
            }
        }
        __syncthreads();
    }
}

// ---------------- fused edge kernel (fp16 everything + FUSED E stats) -----------
__global__ __launch_bounds__(256, 3)
void edge_kernel(const float* __restrict__ EXin, const __half* __restrict__ Wt,
                 const float* __restrict__ bias,
                 const int* __restrict__ src, const int* __restrict__ dst,
                 const float* __restrict__ sne,
                 const __half* __restrict__ BX, const __half* __restrict__ DXn,
                 const __half* __restrict__ EXn,
                 __half* __restrict__ num, __half* __restrict__ den,
                 __half* __restrict__ outE16,
                 float* __restrict__ esum, float* __restrict__ esq) {
    extern __shared__ uint32_t smemu[];
    __shared__ int   s_src[BLK_M];
    __shared__ int   s_dst[BLK_M];
    __shared__ float s_sn[BLK_M];
    __shared__ float sm1[128];
    __shared__ float sm2[128];
    uint32_t* Csu = smemu;

    int tid = threadIdx.x;
    int lane = tid & 31;
    int rowBase = blockIdx.x * BLK_M;

    if (tid < BLK_M) {
        int e = min(rowBase + tid, N_EDGES - 1);
        s_src[tid] = src[e];
        s_dst[tid] = dst[e];
        s_sn[tid]  = sne[e];
    }
    if (tid < 128) { sm1[tid] = 0.f; sm2[tid] = 0.f; }

    float acc[2][4][4];
    gemm_f16<true>(EXin, Wt, rowBase, N_EDGES, smemu, acc, tid);

    #pragma unroll
    for (int h32 = 0; h32 < 2; h32++) {
        store_h16(Csu, acc, h32, tid);
        __syncthreads();
        int r = tid >> 3, q = tid & 7;
        long e = (long)rowBase + h32 * 32 + r;
        bool valid = (e < N_EDGES);

        // read this thread's 16 result columns (fp16 pairs)
        uint4 cu0 = *(uint4*)&Csu[r * CS_U32 + q * 8];
        uint4 cu1 = *(uint4*)&Csu[r * CS_U32 + q * 8 + 4];
        uint32_t cw[8] = {cu0.x, cu0.y, cu0.z, cu0.w, cu1.x, cu1.y, cu1.z, cu1.w};

        int sv = 0, dv = 0;
        float sn = 0.f;
        if (valid) {
            sv = s_src[h32 * 32 + r];
            dv = s_dst[h32 * 32 + r];
            sn = s_sn[h32 * 32 + r];
        }
        const __half* dxp = &DXn[(long)sv * 128];
        const __half* exp_ = &EXn[(long)dv * 128];
        const __half* bxp = &BX[(long)sv * 128];
        __half* np = &num[(long)dv * 128];
        __half* dp = &den[(long)dv * 128];
        __half* op = &outE16[e * 128];

        #pragma unroll
        for (int cb = 0; cb < 4; cb++) {
            int c = q * 16 + cb * 4;
            float epv[4] = {0.f, 0.f, 0.f, 0.f};
            if (valid) {
                float2 c0 = __half22float2(*reinterpret_cast<__half2*>(&cw[cb * 2]));
                float2 c1 = __half22float2(*reinterpret_cast<__half2*>(&cw[cb * 2 + 1]));
                float4 bb = __ldg((const float4*)&bias[c]);
                uint2 du = *(const uint2*)&dxp[c];
                uint2 eu = *(const uint2*)&exp_[c];
                uint2 bu = *(const uint2*)&bxp[c];
                float2 d0 = __half22float2(*reinterpret_cast<__half2*>(&du.x));
                float2 d1 = __half22float2(*reinterpret_cast<__half2*>(&du.y));
                float2 e0 = __half22float2(*reinterpret_cast<__half2*>(&eu.x));
                float2 e1 = __half22float2(*reinterpret_cast<__half2*>(&eu.y));
                float2 b0 = __half22float2(*reinterpret_cast<__half2*>(&bu.x));
                float2 b1 = __half22float2(*reinterpret_cast<__half2*>(&bu.y));
                float cev[4] = {c0.x, c0.y, c1.x, c1.y};
                float bbv[4] = {bb.x, bb.y, bb.z, bb.w};
                float dxv[4] = {d0.x, d0.y, d1.x, d1.y};
                float exv[4] = {e0.x, e0.y, e1.x, e1.y};
                float bxv[4] = {b0.x, b0.y, b1.x, b1.y};
                float ej[4], sg[4], nb[4];
                #pragma unroll
                for (int j = 0; j < 4; j++) {
                    ej[j] = cev[j] + bbv[j] + dxv[j] + exv[j];
                    sg[j] = 1.f / (1.f + __expf(-ej[j]));
                    nb[j] = sg[j] * bxv[j];
                    epv[j] = ej[j] * sn;
                }
                uint2 pu;
                pu.x = h2bits(__floats2half2_rn(epv[0], epv[1]));
                pu.y = h2bits(__floats2half2_rn(epv[2], epv[3]));
                __stcs((uint2*)&op[c], pu);
                red_add_h4(np + c, h2bits(__floats2half2_rn(nb[0], nb[1])),
                                   h2bits(__floats2half2_rn(nb[2], nb[3])));
                red_add_h4(dp + c, h2bits(__floats2half2_rn(sg[0], sg[1])),
                                   h2bits(__floats2half2_rn(sg[2], sg[3])));
            }
            // fused column stats: lanes {l, l^8, l^16, l^24} share column group q
            #pragma unroll
            for (int j = 0; j < 4; j++) {
                float s  = epv[j];
                float sq = s * s;
                s  += __shfl_xor_sync(0xffffffffu, s, 8);
                s  += __shfl_xor_sync(0xffffffffu, s, 16);
                sq += __shfl_xor_sync(0xffffffffu, sq, 8);
                sq += __shfl_xor_sync(0xffffffffu, sq, 16);
                if (lane < 8) {
                    atomicAdd(&sm1[c + j], s);
                    atomicAdd(&sm2[c + j], sq);
                }
            }
        }
        __syncthreads();
    }

    // flush block stats to global
    if (tid < 128) {
        atomicAdd(&esum[tid], sm1[tid]);
        atomicAdd(&esq[tid],  sm2[tid]);
    }
}

// ---------------- node pre-BN (fp16 num/den; den>0 detects in-degree) -----------
__global__ void node_pre(const float* __restrict__ X, const float* __restrict__ AX,
                         const __half* __restrict__ num, const __half* __restrict__ den,
                         const float* __restrict__ snorm_n,
                         float* __restrict__ outH,
                         float* __restrict__ hsum, float* __restrict__ hsq) {
    __shared__ float sm1[128];
    __shared__ float sm2[128];
    int tid = threadIdx.x;
    if (tid < 128) { sm1[tid] = 0.f; sm2[tid] = 0.f; }
    __syncthreads();

    int c2 = tid & 63;
    int rl = tid >> 6;
    int rBase = blockIdx.x * 64;
    int rEnd = min(rBase + 64, N_NODES);

    float a1 = 0.f, a2 = 0.f, b1 = 0.f, b2 = 0.f;
    for (int r = rBase + rl; r < rEnd; r += 4) {
        float sn = snorm_n[r];
        long idx2 = (long)r * 64 + c2;
        long idxf = (long)r * 128 + c2 * 2;
        __half2 nh = *reinterpret_cast<const __half2*>(&num[idx2 * 2]);
        __half2 dh = *reinterpret_cast<const __half2*>(&den[idx2 * 2]);
        float2 nf = __half22float2(nh);
        float2 df = __half22float2(dh);
        float2 ax = *(const float2*)&AX[idxf];
        float2 xx = *(const float2*)&X[idxf];
        float h0 = (df.x > 0.f) ? (ax.x + nf.x / df.x) : xx.x;
        float h1 = (df.y > 0.f) ? (ax.y + nf.y / df.y) : xx.y;
        h0 *= sn; h1 *= sn;
        *(float2*)&outH[idxf] = make_float2(h0, h1);
        a1 += h0; a2 += h0 * h0;
        b1 += h1; b2 += h1 * h1;
    }
    atomicAdd(&sm1[c2 * 2],     a1);
    atomicAdd(&sm2[c2 * 2],     a2);
    atomicAdd(&sm1[c2 * 2 + 1], b1);
    atomicAdd(&sm2[c2 * 2 + 1], b2);
    __syncthreads();
    if (tid < 128) atomicAdd(&hsum[tid], sm1[tid]);
    else           atomicAdd(&hsq[tid - 128], sm2[tid - 128]);
}

// ---------------- finalize H: out = X + relu(BN(pre)) (float path, in-place) ----
__global__ void finalize_bn(const float* __restrict__ base, float* __restrict__ pre,
                            const float* __restrict__ sum, const float* __restrict__ sq,
                            const float* __restrict__ gamma, const float* __restrict__ beta,
                            long total4, float invn) {
    long i = (long)blockIdx.x * blockDim.x + threadIdx.x;
    if (i >= total4) return;
    int c4 = (int)(i & 31) * 4;
    float4 v  = __ldcs(&((const float4*)pre)[i]);
    float4 xv = __ldcs(&((const float4*)base)[i]);
    float vv[4] = {v.x, v.y, v.z, v.w};
    float xx[4] = {xv.x, xv.y, xv.z, xv.w};
    float oo[4];
    #pragma unroll
    for (int j = 0; j < 4; j++) {
        int c = c4 + j;
        float m   = __ldg(&sum[c]) * invn;
        float var = __ldg(&sq[c]) * invn - m * m;
        float rs  = rsqrtf(var + BN_EPS);
        float t = (vv[j] - m) * rs * __ldg(&gamma[c]) + __ldg(&beta[c]);
        oo[j] = xx[j] + fmaxf(t, 0.f);
    }
    __stcs(&((float4*)pre)[i], make_float4(oo[0], oo[1], oo[2], oo[3]));
}

// ---------------- finalize E: out = E_X + relu(BN(E16)) -------------------------
__global__ void finalize_e(const float4* __restrict__ base, const uint4* __restrict__ E16,
                           float4* __restrict__ out,
                           const float* __restrict__ sum, const float* __restrict__ sq,
                           const float* __restrict__ gamma, const float* __restrict__ beta) {
    long i = (long)blockIdx.x * blockDim.x + threadIdx.x;    // one per 8 elems
    if (i >= (long)N_EDGES * 16) return;
    int c8 = (int)(i & 15) * 8;
    const float invn = 1.f / N_EDGES;

    uint4 u = __ldcs(&E16[i]);
    uint32_t uw[4] = {u.x, u.y, u.z, u.w};
    float4 x0 = __ldcs(&base[i * 2]);
    float4 x1 = __ldcs(&base[i * 2 + 1]);
    float xx[8] = {x0.x, x0.y, x0.z, x0.w, x1.x, x1.y, x1.z, x1.w};
    float oo[8];
    #pragma unroll
    for (int p = 0; p < 4; p++) {
        __half2 h = *reinterpret_cast<__half2*>(&uw[p]);
        float2 f = __half22float2(h);
        float vv[2] = {f.x, f.y};
        #pragma unroll
        for (int q = 0; q < 2; q++) {
            int j = p * 2 + q;
            int c = c8 + j;
            float m   = __ldg(&sum[c]) * invn;
            float var = __ldg(&sq[c]) * invn - m * m;
            float rs  = rsqrtf(var + BN_EPS);
            float t = (vv[q] - m) * rs * __ldg(&gamma[c]) + __ldg(&beta[c]);
            oo[j] = xx[j] + fmaxf(t, 0.f);
        }
    }
    __stcs(&out[i * 2],     make_float4(oo[0], oo[1], oo[2], oo[3]));
    __stcs(&out[i * 2 + 1], make_float4(oo[4], oo[5], oo[6], oo[7]));
}

// ---------------- launch --------------------------------------------------------
extern "C" void kernel_launch(void* const* d_in, const int* in_sizes, int n_in,
                              void* d_out, int out_size) {
    const float* X       = (const float*)d_in[0];
    const float* E_X     = (const float*)d_in[1];
    const int*   src     = (const int*)  d_in[2];
    const int*   dst     = (const int*)  d_in[3];
    const float* snorm_n = (const float*)d_in[4];
    const float* snorm_e = (const float*)d_in[5];
    const float* WA = (const float*)d_in[6];
    const float* bA = (const float*)d_in[7];
    const float* WB = (const float*)d_in[8];
    const float* bB = (const float*)d_in[9];
    const float* WC = (const float*)d_in[10];
    const float* bC = (const float*)d_in[11];
    const float* WD = (const float*)d_in[12];
    const float* bD = (const float*)d_in[13];
    const float* WE = (const float*)d_in[14];
    const float* bE = (const float*)d_in[15];
    const float* gamma_h = (const float*)d_in[16];
    const float* beta_h  = (const float*)d_in[17];
    const float* gamma_e = (const float*)d_in[18];
    const float* beta_e  = (const float*)d_in[19];

    float* out  = (float*)d_out;
    float* outH = out;
    float* outE = out + (long)N_NODES * DIM;

    float *pAX;
    __half *pBX, *pDX, *pEX, *pnum, *pden, *pE16, *pWt;
    float *phsum, *phsq, *pesum, *pesq;
    cudaGetSymbolAddress((void**)&pAX, g_AX);
    cudaGetSymbolAddress((void**)&pBX, g_BX);
    cudaGetSymbolAddress((void**)&pDX, g_DX);
    cudaGetSymbolAddress((void**)&pEX, g_EX);
    cudaGetSymbolAddress((void**)&pnum, g_num);
    cudaGetSymbolAddress((void**)&pden, g_den);
    cudaGetSymbolAddress((void**)&pE16, g_E16);
    cudaGetSymbolAddress((void**)&pWt, g_Wt);
    cudaGetSymbolAddress((void**)&phsum, g_hsum);
    cudaGetSymbolAddress((void**)&phsq, g_hsq);
    cudaGetSymbolAddress((void**)&pesum, g_esum);
    cudaGetSymbolAddress((void**)&pesq, g_esq);

    // allow 52KB dynamic smem (host-side, idempotent, not captured)
    static bool attr_set = false;
    if (!attr_set) {
        cudaFuncSetAttribute(gemm_bias, cudaFuncAttributeMaxDynamicSharedMemorySize, SMEM_G_BYTES);
        cudaFuncSetAttribute(edge_kernel, cudaFuncAttributeMaxDynamicSharedMemorySize, SMEM_G_BYTES);
        attr_set = true;
    }

    // 1. zero scratch + Wt prep (order: A, B, D, E, C)
    zero_scratch<<<3125, 256>>>((uint4*)pnum, (uint4*)pden,
                                phsum, phsq, pesum, pesq);
    wt_prep<<<160, 256>>>(WA, WB, WD, WE, WC, (__half2*)pWt);

    // 2. node GEMMs (fp16 MMA; AX fp32 out; BX/DX/EX fp16 out)
    dim3 ngrid((N_NODES + BLK_M - 1) / BLK_M, 4);   // 782 x 4
    gemm_bias<<<ngrid, 256, SMEM_G_BYTES>>>(X, pWt,
                                            bA, pAX,
                                            bB, pBX,
                                            bD, pDX,
                                            bE, pEX,
                                            N_NODES);

    // 3. fused edge kernel (CE GEMM + message + gated scatter + E stats)
    int edgeBlocks = (N_EDGES + BLK_M - 1) / BLK_M;   // 7813
    edge_kernel<<<edgeBlocks, 256, SMEM_G_BYTES>>>(E_X, pWt + 4L * DIM * DIM, bC,
                                                   src, dst, snorm_e,
                                                   pBX, pDX, pEX, pnum, pden, pE16,
                                                   pesum, pesq);

    // 4. node combine + H stats (fp16 num/den)
    node_pre<<<(N_NODES + 63) / 64, 256>>>(X, pAX, pnum, pden, snorm_n,
                                           outH, phsum, phsq);

    // 5. finalize H: out = X + relu(BN(Hpre))  (in-place float path)
    long h4 = (long)N_NODES * DIM / 4;       // 1.6M
    finalize_bn<<<(int)((h4 + 255) / 256), 256>>>(X, outH, phsum, phsq,
                                                  gamma_h, beta_h, h4, 1.f / N_NODES);

    // 6. finalize E: out = E_X + relu(BN(E16))
    long e8 = (long)N_EDGES * 16;            // 8M groups of 8 elems
    finalize_e<<<(int)((e8 + 255) / 256), 256>>>((const float4*)E_X, (const uint4*)pE16,
                                                 (float4*)outE, pesum, pesq,
                                                 gamma_e, beta_e);
}

// round 17
// speedup vs baseline: 1.2405x; 1.2405x over previous
#include <cuda_runtime.h>
#include <cuda_fp16.h>
#include <math.h>
#include <stdint.h>

#define N_NODES 50000
#define N_EDGES 500000
#define DIM 128
#define BN_EPS 1e-5f

#define BLK_M 64
#define AS_U32 68        // A smem row stride in uint32 (64 half2 + 4 pad) — bank-clean
#define WS_U32 68        // W smem row stride in uint32
#define CS_STRIDE 136    // 32 rows x 128 cols fp32, padded
#define SMEM_G_BYTES ((BLK_M * AS_U32 + 128 * WS_U32) * 4)   // 52224 B

// ---------------- scratch (device globals; no allocations allowed) ----------
__device__ float  g_AX[N_NODES * DIM];            // fp32 (feeds H path directly)
__device__ __half g_BX[N_NODES * DIM];            // fp16 gather arrays
__device__ __half g_DX[N_NODES * DIM];
__device__ __half g_EX[N_NODES * DIM];
__device__ __half g_num[N_NODES * DIM];           // fp16 atomic reduction targets
__device__ __half g_den[N_NODES * DIM];
__device__ __half g_E16[(size_t)N_EDGES * DIM];   // fp16 Epre intermediate
__device__ __half g_Wt[5 * DIM * DIM];            // fp16 n-major weights: A,B,D,E,C
__device__ float  g_hsum[DIM];
__device__ float  g_hsq[DIM];
__device__ float  g_esum[DIM];
__device__ float  g_esq[DIM];

// ---------------- helpers ----------------------------------------------------
__device__ __forceinline__ void red_add_h4(__half* addr, uint32_t h01, uint32_t h23) {
    asm volatile("red.global.add.noftz.v2.f16x2 [%0], {%1, %2};"
                 :: "l"(addr), "r"(h01), "r"(h23)
                 : "memory");
}

__device__ __forceinline__ void mma_f16(float c[4],
                                        uint32_t a0, uint32_t a1, uint32_t a2, uint32_t a3,
                                        uint32_t b0, uint32_t b1) {
    asm volatile("mma.sync.aligned.m16n8k16.row.col.f32.f16.f16.f32 "
                 "{%0,%1,%2,%3},{%4,%5,%6,%7},{%8,%9},{%0,%1,%2,%3};"
                 : "+f"(c[0]), "+f"(c[1]), "+f"(c[2]), "+f"(c[3])
                 : "r"(a0), "r"(a1), "r"(a2), "r"(a3), "r"(b0), "r"(b1));
}

__device__ __forceinline__ uint32_t h2bits(__half2 h) {
    return *reinterpret_cast<uint32_t*>(&h);
}

// ---------------- Wt prep: W[k][n] fp32 -> Wt[n][k] fp16 (n-major) --------------
__global__ void wt_prep(const float* __restrict__ W0, const float* __restrict__ W1,
                        const float* __restrict__ W2, const float* __restrict__ W3,
                        const float* __restrict__ W4, __half2* __restrict__ Wt) {
    int gid = blockIdx.x * 256 + threadIdx.x;     // 5*128*64 = 40960
    if (gid >= 5 * 128 * 64) return;
    int k2 = gid & 63;
    int n  = (gid >> 6) & 127;
    int w  = gid >> 13;
    const float* W = (w == 0) ? W0 : (w == 1) ? W1 : (w == 2) ? W2 : (w == 3) ? W3 : W4;
    Wt[gid] = __floats2half2_rn(W[(2 * k2) * 128 + n], W[(2 * k2 + 1) * 128 + n]);
}

// ================================================================================
// FP16 tensor-core GEMM core (R15-proven): 64x128 tile, 256 threads, 8 warps
// (2 row-groups x 4 col-groups; warp tile 32x32, acc[2][4][4] fp32). m16n8k16.
// A staged once (fp32->fp16 inline), W staged once from prepacked fp16 Wt.
// ================================================================================
template <bool STREAM_A>
__device__ __forceinline__ void gemm_f16(const float* __restrict__ A,
                                         const __half* __restrict__ Wt,
                                         int rowBase, int M, uint32_t* smemu,
                                         float acc[2][4][4], int tid) {
    int lane = tid & 31, wid = tid >> 5;
    int wr = wid & 1, wc = wid >> 1;
    uint32_t* Asu = smemu;
    uint32_t* Wsu = smemu + BLK_M * AS_U32;
    const uint32_t* Wtu = (const uint32_t*)Wt;

    #pragma unroll
    for (int h = 0; h < 2; h++)
        #pragma unroll
        for (int t = 0; t < 4; t++)
            #pragma unroll
            for (int j = 0; j < 4; j++) acc[h][t][j] = 0.f;

    #pragma unroll
    for (int u = 0; u < 8; u++) {
        int idx = tid + u * 256;
        int r  = idx >> 5;
        int c4 = idx & 31;
        int gr = min(rowBase + r, M - 1);
        const float4* ap = &((const float4*)A)[(long)gr * 32 + c4];
        float4 v = STREAM_A ? __ldcs(ap) : *ap;
        uint2 st;
        st.x = h2bits(__floats2half2_rn(v.x, v.y));
        st.y = h2bits(__floats2half2_rn(v.z, v.w));
        *(uint2*)&Asu[r * AS_U32 + c4 * 2] = st;
    }
    #pragma unroll
    for (int u = 0; u < 8; u++) {
        int idx = tid + u * 256;
        int n  = idx >> 4;
        int q4 = idx & 15;
        uint4 v = *(const uint4*)&Wtu[n * 64 + q4 * 4];
        *(uint4*)&Wsu[n * WS_U32 + q4 * 4] = v;
    }
    __syncthreads();

    int akl = lane & 3;
    int aro = lane >> 2;

    #pragma unroll
    for (int ks = 0; ks < 8; ks++) {
        int kb = ks * 8;
        uint32_t a[2][4];
        #pragma unroll
        for (int h = 0; h < 2; h++) {
            int r = wr * 32 + h * 16 + aro;
            a[h][0] = Asu[r * AS_U32 + kb + akl];
            a[h][1] = Asu[(r + 8) * AS_U32 + kb + akl];
            a[h][2] = Asu[r * AS_U32 + kb + 4 + akl];
            a[h][3] = Asu[(r + 8) * AS_U32 + kb + 4 + akl];
        }
        #pragma unroll
        for (int t = 0; t < 4; t++) {
            int n = wc * 32 + t * 8 + aro;
            uint32_t b0 = Wsu[n * WS_U32 + kb + akl];
            uint32_t b1 = Wsu[n * WS_U32 + kb + 4 + akl];
            mma_f16(acc[0][t], a[0][0], a[0][1], a[0][2], a[0][3], b0, b1);
            mma_f16(acc[1][t], a[1][0], a[1][1], a[1][2], a[1][3], b0, b1);
        }
    }
    __syncthreads();
}

// store the warp's rows belonging to [h32*32, h32*32+32) into Cs[32][CS_STRIDE]
__device__ __forceinline__ void store_half32(float* Cs, float acc[2][4][4], int h32, int tid) {
    int lane = tid & 31, wid = tid >> 5;
    int wr = wid & 1, wc = wid >> 1;
    if (wr == h32) {
        #pragma unroll
        for (int h = 0; h < 2; h++) {
            int lr = h * 16 + (lane >> 2);
            #pragma unroll
            for (int t = 0; t < 4; t++) {
                int c = wc * 32 + t * 8 + 2 * (lane & 3);
                *(float2*)&Cs[lr * CS_STRIDE + c]       = make_float2(acc[h][t][0], acc[h][t][1]);
                *(float2*)&Cs[(lr + 8) * CS_STRIDE + c] = make_float2(acc[h][t][2], acc[h][t][3]);
            }
        }
    }
}

// ---------------- zero scratch (num/den are half: 800k uint4 each) --------------
__global__ void zero_scratch(uint4* num4, uint4* den4,
                             float* hsum, float* hsq, float* esum, float* esq) {
    int i = blockIdx.x * blockDim.x + threadIdx.x;   // exactly 800,000 threads
    uint4 z = make_uint4(0u, 0u, 0u, 0u);
    num4[i] = z;
    den4[i] = z;
    if (i < DIM) { hsum[i] = 0.f; hsq[i] = 0.f; esum[i] = 0.f; esq[i] = 0.f; }
}

// ---------------- fused node GEMMs (fp16 MMA; AX fp32, B/D/E fp16 out) ----------
__global__ __launch_bounds__(256, 3)
void gemm_bias(const float* __restrict__ A, const __half* __restrict__ Wt,
               const float* __restrict__ b0p, float*  __restrict__ o0,
               const float* __restrict__ b1p, __half* __restrict__ o1,
               const float* __restrict__ b2p, __half* __restrict__ o2,
               const float* __restrict__ b3p, __half* __restrict__ o3,
               int M) {
    extern __shared__ uint32_t smemu[];
    float* Cs = (float*)smemu;   // alias after GEMM (32 x 136 fp32 = 17408 B fits in As)

    const float* bias;
    float*  outf = 0;
    __half* outh = 0;
    switch (blockIdx.y) {
        case 0:  bias = b0p; outf = o0; break;
        case 1:  bias = b1p; outh = o1; break;
        case 2:  bias = b2p; outh = o2; break;
        default: bias = b3p; outh = o3; break;
    }
    const __half* Wtw = Wt + (long)blockIdx.y * DIM * DIM;
    int tid = threadIdx.x;
    int rowBase = blockIdx.x * BLK_M;

    float acc[2][4][4];
    gemm_f16<false>(A, Wtw, rowBase, M, smemu, acc, tid);

    #pragma unroll
    for (int h32 = 0; h32 < 2; h32++) {
        store_half32(Cs, acc, h32, tid);
        __syncthreads();
        int r = tid >> 3, q = tid & 7;
        int grow = rowBase + h32 * 32 + r;
        if (grow < M) {
            #pragma unroll
            for (int cb = 0; cb < 4; cb++) {
                int c = q * 16 + cb * 4;
                float4 v = *(float4*)&Cs[r * CS_STRIDE + c];
                float4 bb = __ldg((const float4*)&bias[c]);
                v.x += bb.x; v.y += bb.y; v.z += bb.z; v.w += bb.w;
                if (blockIdx.y == 0) {
                    *(float4*)&outf[(long)grow * 128 + c] = v;
                } else {
                    uint2 u;
                    u.x = h2bits(__floats2half2_rn(v.x, v.y));
                    u.y = h2bits(__floats2half2_rn(v.z, v.w));
                    *(uint2*)&outh[(long)grow * 128 + c] = u;
                }
            }
        }
        __syncthreads();
    }
}

// ---------------- fused edge kernel (fp16 MMA, fp16 gathers/Epre/red) -----------
__global__ __launch_bounds__(256, 3)
void edge_kernel(const float* __restrict__ EXin, const __half* __restrict__ Wt,
                 const float* __restrict__ bias,
                 const int* __restrict__ src, const int* __restrict__ dst,
                 const float* __restrict__ sne,
                 const __half* __restrict__ BX, const __half* __restrict__ DXn,
                 const __half* __restrict__ EXn,
                 __half* __restrict__ num, __half* __restrict__ den,
                 __half* __restrict__ outE16) {
    extern __shared__ uint32_t smemu[];
    __shared__ int   s_src[BLK_M];
    __shared__ int   s_dst[BLK_M];
    __shared__ float s_sn[BLK_M];
    float* Cs = (float*)smemu;

    int tid = threadIdx.x;
    int rowBase = blockIdx.x * BLK_M;

    if (tid < BLK_M) {
        int e = min(rowBase + tid, N_EDGES - 1);
        s_src[tid] = src[e];
        s_dst[tid] = dst[e];
        s_sn[tid]  = sne[e];
    }

    float acc[2][4][4];
    gemm_f16<true>(EXin, Wt, rowBase, N_EDGES, smemu, acc, tid);

    #pragma unroll
    for (int h32 = 0; h32 < 2; h32++) {
        store_half32(Cs, acc, h32, tid);
        __syncthreads();
        int r = tid >> 3, q = tid & 7;
        long e = (long)rowBase + h32 * 32 + r;
        if (e < N_EDGES) {
            int sv = s_src[h32 * 32 + r];
            int dv = s_dst[h32 * 32 + r];
            float sn = s_sn[h32 * 32 + r];
            const __half* dxp = &DXn[(long)sv * 128];
            const __half* exp_ = &EXn[(long)dv * 128];
            const __half* bxp = &BX[(long)sv * 128];
            __half* np = &num[(long)dv * 128];
            __half* dp = &den[(long)dv * 128];
            __half* op = &outE16[e * 128];
            #pragma unroll
            for (int cb = 0; cb < 4; cb++) {
                int c = q * 16 + cb * 4;
                float4 ce = *(float4*)&Cs[r * CS_STRIDE + c];
                float4 bb = __ldg((const float4*)&bias[c]);
                uint2 du = *(const uint2*)&dxp[c];
                uint2 eu = *(const uint2*)&exp_[c];
                uint2 bu = *(const uint2*)&bxp[c];
                float2 d0 = __half22float2(*reinterpret_cast<__half2*>(&du.x));
                float2 d1 = __half22float2(*reinterpret_cast<__half2*>(&du.y));
                float2 e0 = __half22float2(*reinterpret_cast<__half2*>(&eu.x));
                float2 e1 = __half22float2(*reinterpret_cast<__half2*>(&eu.y));
                float2 b0 = __half22float2(*reinterpret_cast<__half2*>(&bu.x));
                float2 b1 = __half22float2(*reinterpret_cast<__half2*>(&bu.y));
                float dxv[4] = {d0.x, d0.y, d1.x, d1.y};
                float exv[4] = {e0.x, e0.y, e1.x, e1.y};
                float bxv[4] = {b0.x, b0.y, b1.x, b1.y};
                float cev[4] = {ce.x, ce.y, ce.z, ce.w};
                float bbv[4] = {bb.x, bb.y, bb.z, bb.w};
                float ej[4], sg[4], nb[4];
                #pragma unroll
                for (int j = 0; j < 4; j++) {
                    ej[j] = cev[j] + bbv[j] + dxv[j] + exv[j];
                    sg[j] = 1.f / (1.f + __expf(-ej[j]));
                    nb[j] = sg[j] * bxv[j];
                }
                // fp16 Epre store
                uint2 pu;
                pu.x = h2bits(__floats2half2_rn(ej[0] * sn, ej[1] * sn));
                pu.y = h2bits(__floats2half2_rn(ej[2] * sn, ej[3] * sn));
                __stcs((uint2*)&op[c], pu);
                // fp16x2 vector reductions (8B each)
                red_add_h4(np + c, h2bits(__floats2half2_rn(nb[0], nb[1])),
                                   h2bits(__floats2half2_rn(nb[2], nb[3])));
                red_add_h4(dp + c, h2bits(__floats2half2_rn(sg[0], sg[1])),
                                   h2bits(__floats2half2_rn(sg[2], sg[3])));
            }
        }
        __syncthreads();
    }
}

// ---------------- E column stats over fp16 Epre (MLP-4 unrolled) ----------------
__global__ void estats_kernel(const uint4* __restrict__ E16,
                              float* __restrict__ esum, float* __restrict__ esq) {
    __shared__ float sm1[128];
    __shared__ float sm2[128];
    int tid = threadIdx.x;
    int lane = tid & 31;
    if (tid < 128) { sm1[tid] = 0.f; sm2[tid] = 0.f; }
    __syncthreads();

    int c8 = tid & 15;
    int rlane = tid >> 4;
    long G = (long)gridDim.x * 16;

    float s1[8], s2[8];
    #pragma unroll
    for (int j = 0; j < 8; j++) { s1[j] = 0.f; s2[j] = 0.f; }

    for (long r = (long)blockIdx.x * 16 + rlane; r < N_EDGES; r += 4 * G) {
        uint4 u[4];
        bool vld[4];
        #pragma unroll
        for (int k = 0; k < 4; k++) {
            long rr = r + k * G;
            vld[k] = (rr < N_EDGES);
            if (vld[k]) u[k] = __ldcs(&E16[rr * 16 + c8]);
        }
        #pragma unroll
        for (int k = 0; k < 4; k++) {
            if (vld[k]) {
                uint32_t uw[4] = {u[k].x, u[k].y, u[k].z, u[k].w};
                #pragma unroll
                for (int p = 0; p < 4; p++) {
                    __half2 h = *reinterpret_cast<__half2*>(&uw[p]);
                    float2 f = __half22float2(h);
                    s1[p * 2]     += f.x;  s2[p * 2]     += f.x * f.x;
                    s1[p * 2 + 1] += f.y;  s2[p * 2 + 1] += f.y * f.y;
                }
            }
        }
    }
    #pragma unroll
    for (int j = 0; j < 8; j++) {
        s1[j] += __shfl_xor_sync(0xffffffffu, s1[j], 16);
        s2[j] += __shfl_xor_sync(0xffffffffu, s2[j], 16);
    }
    if (lane < 16) {
        #pragma unroll
        for (int j = 0; j < 8; j++) {
            atomicAdd(&sm1[c8 * 8 + j], s1[j]);
            atomicAdd(&sm2[c8 * 8 + j], s2[j]);
        }
    }
    __syncthreads();
    if (tid < 128) atomicAdd(&esum[tid], sm1[tid]);
    else           atomicAdd(&esq[tid - 128], sm2[tid - 128]);
}

// ---------------- node pre-BN (fp16 num/den; den>0 detects in-degree) -----------
__global__ void node_pre(const float* __restrict__ X, const float* __restrict__ AX,
                         const __half* __restrict__ num, const __half* __restrict__ den,
                         const float* __restrict__ snorm_n,
                         float* __restrict__ outH,
                         float* __restrict__ hsum, float* __restrict__ hsq) {
    __shared__ float sm1[128];
    __shared__ float sm2[128];
    int tid = threadIdx.x;
    if (tid < 128) { sm1[tid] = 0.f; sm2[tid] = 0.f; }
    __syncthreads();

    int c2 = tid & 63;
    int rl = tid >> 6;
    int rBase = blockIdx.x * 64;
    int rEnd = min(rBase + 64, N_NODES);

    float a1 = 0.f, a2 = 0.f, b1 = 0.f, b2 = 0.f;
    for (int r = rBase + rl; r < rEnd; r += 4) {
        float sn = snorm_n[r];
        long idx2 = (long)r * 64 + c2;
        long idxf = (long)r * 128 + c2 * 2;
        __half2 nh = *reinterpret_cast<const __half2*>(&num[idx2 * 2]);
        __half2 dh = *reinterpret_cast<const __half2*>(&den[idx2 * 2]);
        float2 nf = __half22float2(nh);
        float2 df = __half22float2(dh);
        float2 ax = *(const float2*)&AX[idxf];
        float2 xx = *(const float2*)&X[idxf];
        float h0 = (df.x > 0.f) ? (ax.x + nf.x / df.x) : xx.x;
        float h1 = (df.y > 0.f) ? (ax.y + nf.y / df.y) : xx.y;
        h0 *= sn; h1 *= sn;
        *(float2*)&outH[idxf] = make_float2(h0, h1);
        a1 += h0; a2 += h0 * h0;
        b1 += h1; b2 += h1 * h1;
    }
    atomicAdd(&sm1[c2 * 2],     a1);
    atomicAdd(&sm2[c2 * 2],     a2);
    atomicAdd(&sm1[c2 * 2 + 1], b1);
    atomicAdd(&sm2[c2 * 2 + 1], b2);
    __syncthreads();
    if (tid < 128) atomicAdd(&hsum[tid], sm1[tid]);
    else           atomicAdd(&hsq[tid - 128], sm2[tid - 128]);
}

// ---------------- finalize H: out = X + relu(BN(pre)) (float path, in-place) ----
__global__ void finalize_bn(const float* __restrict__ base, float* __restrict__ pre,
                            const float* __restrict__ sum, const float* __restrict__ sq,
                            const float* __restrict__ gamma, const float* __restrict__ beta,
                            long total4, float invn) {
    long i = (long)blockIdx.x * blockDim.x + threadIdx.x;
    if (i >= total4) return;
    int c4 = (int)(i & 31) * 4;
    float4 v  = __ldcs(&((const float4*)pre)[i]);
    float4 xv = __ldcs(&((const float4*)base)[i]);
    float vv[4] = {v.x, v.y, v.z, v.w};
    float xx[4] = {xv.x, xv.y, xv.z, xv.w};
    float oo[4];
    #pragma unroll
    for (int j = 0; j < 4; j++) {
        int c = c4 + j;
        float m   = __ldg(&sum[c]) * invn;
        float var = __ldg(&sq[c]) * invn - m * m;
        float rs  = rsqrtf(var + BN_EPS);
        float t = (vv[j] - m) * rs * __ldg(&gamma[c]) + __ldg(&beta[c]);
        oo[j] = xx[j] + fmaxf(t, 0.f);
    }
    __stcs(&((float4*)pre)[i], make_float4(oo[0], oo[1], oo[2], oo[3]));
}

// ---------------- finalize E: out = E_X + relu(BN(E16)) -------------------------
__global__ void finalize_e(const float4* __restrict__ base, const uint4* __restrict__ E16,
                           float4* __restrict__ out,
                           const float* __restrict__ sum, const float* __restrict__ sq,
                           const float* __restrict__ gamma, const float* __restrict__ beta) {
    long i = (long)blockIdx.x * blockDim.x + threadIdx.x;    // one per 8 elems
    if (i >= (long)N_EDGES * 16) return;
    int c8 = (int)(i & 15) * 8;
    const float invn = 1.f / N_EDGES;

    uint4 u = __ldcs(&E16[i]);
    uint32_t uw[4] = {u.x, u.y, u.z, u.w};
    float4 x0 = __ldcs(&base[i * 2]);
    float4 x1 = __ldcs(&base[i * 2 + 1]);
    float xx[8] = {x0.x, x0.y, x0.z, x0.w, x1.x, x1.y, x1.z, x1.w};
    float oo[8];
    #pragma unroll
    for (int p = 0; p < 4; p++) {
        __half2 h = *reinterpret_cast<__half2*>(&uw[p]);
        float2 f = __half22float2(h);
        float vv[2] = {f.x, f.y};
        #pragma unroll
        for (int q = 0; q < 2; q++) {
            int j = p * 2 + q;
            int c = c8 + j;
            float m   = __ldg(&sum[c]) * invn;
            float var = __ldg(&sq[c]) * invn - m * m;
            float rs  = rsqrtf(var + BN_EPS);
            float t = (vv[q] - m) * rs * __ldg(&gamma[c]) + __ldg(&beta[c]);
            oo[j] = xx[j] + fmaxf(t, 0.f);
        }
    }
    __stcs(&out[i * 2],     make_float4(oo[0], oo[1], oo[2], oo[3]));
    __stcs(&out[i * 2 + 1], make_float4(oo[4], oo[5], oo[6], oo[7]));
}

// ---------------- launch --------------------------------------------------------
extern "C" void kernel_launch(void* const* d_in, const int* in_sizes, int n_in,
                              void* d_out, int out_size) {
    const float* X       = (const float*)d_in[0];
    const float* E_X     = (const float*)d_in[1];
    const int*   src     = (const int*)  d_in[2];
    const int*   dst     = (const int*)  d_in[3];
    const float* snorm_n = (const float*)d_in[4];
    const float* snorm_e = (const float*)d_in[5];
    const float* WA = (const float*)d_in[6];
    const float* bA = (const float*)d_in[7];
    const float* WB = (const float*)d_in[8];
    const float* bB = (const float*)d_in[9];
    const float* WC = (const float*)d_in[10];
    const float* bC = (const float*)d_in[11];
    const float* WD = (const float*)d_in[12];
    const float* bD = (const float*)d_in[13];
    const float* WE = (const float*)d_in[14];
    const float* bE = (const float*)d_in[15];
    const float* gamma_h = (const float*)d_in[16];
    const float* beta_h  = (const float*)d_in[17];
    const float* gamma_e = (const float*)d_in[18];
    const float* beta_e  = (const float*)d_in[19];

    float* out  = (float*)d_out;
    float* outH = out;
    float* outE = out + (long)N_NODES * DIM;

    float *pAX;
    __half *pBX, *pDX, *pEX, *pnum, *pden, *pE16, *pWt;
    float *phsum, *phsq, *pesum, *pesq;
    cudaGetSymbolAddress((void**)&pAX, g_AX);
    cudaGetSymbolAddress((void**)&pBX, g_BX);
    cudaGetSymbolAddress((void**)&pDX, g_DX);
    cudaGetSymbolAddress((void**)&pEX, g_EX);
    cudaGetSymbolAddress((void**)&pnum, g_num);
    cudaGetSymbolAddress((void**)&pden, g_den);
    cudaGetSymbolAddress((void**)&pE16, g_E16);
    cudaGetSymbolAddress((void**)&pWt, g_Wt);
    cudaGetSymbolAddress((void**)&phsum, g_hsum);
    cudaGetSymbolAddress((void**)&phsq, g_hsq);
    cudaGetSymbolAddress((void**)&pesum, g_esum);
    cudaGetSymbolAddress((void**)&pesq, g_esq);

    // allow 52KB dynamic smem (host-side, idempotent, not captured)
    static bool attr_set = false;
    if (!attr_set) {
        cudaFuncSetAttribute(gemm_bias, cudaFuncAttributeMaxDynamicSharedMemorySize, SMEM_G_BYTES);
        cudaFuncSetAttribute(edge_kernel, cudaFuncAttributeMaxDynamicSharedMemorySize, SMEM_G_BYTES);
        attr_set = true;
    }

    // 1. zero scratch + Wt prep (order: A, B, D, E, C)
    zero_scratch<<<3125, 256>>>((uint4*)pnum, (uint4*)pden,
                                phsum, phsq, pesum, pesq);
    wt_prep<<<160, 256>>>(WA, WB, WD, WE, WC, (__half2*)pWt);

    // 2. node GEMMs (fp16 MMA; AX fp32 out; BX/DX/EX fp16 out)
    dim3 ngrid((N_NODES + BLK_M - 1) / BLK_M, 4);   // 782 x 4
    gemm_bias<<<ngrid, 256, SMEM_G_BYTES>>>(X, pWt,
                                            bA, pAX,
                                            bB, pBX,
                                            bD, pDX,
                                            bE, pEX,
                                            N_NODES);

    // 3. fused edge kernel (CE GEMM + message + gated scatter, all-fp16 traffic)
    int edgeBlocks = (N_EDGES + BLK_M - 1) / BLK_M;   // 7813
    edge_kernel<<<edgeBlocks, 256, SMEM_G_BYTES>>>(E_X, pWt + 4L * DIM * DIM, bC,
                                                   src, dst, snorm_e,
                                                   pBX, pDX, pEX, pnum, pden, pE16);

    // 4. E column stats (fp16 read, MLP-4)
    estats_kernel<<<2368, 256>>>((const uint4*)pE16, pesum, pesq);

    // 5. node combine + H stats (fp16 num/den)
    node_pre<<<(N_NODES + 63) / 64, 256>>>(X, pAX, pnum, pden, snorm_n,
                                           outH, phsum, phsq);

    // 6. finalize H: out = X + relu(BN(Hpre))  (in-place float path)
    long h4 = (long)N_NODES * DIM / 4;       // 1.6M
    finalize_bn<<<(int)((h4 + 255) / 256), 256>>>(X, outH, phsum, phsq,
                                                  gamma_h, beta_h, h4, 1.f / N_NODES);

    // 7. finalize E: out = E_X + relu(BN(E16))
    long e8 = (long)N_EDGES * 16;            // 8M groups of 8 elems
    finalize_e<<<(int)((e8 + 255) / 256), 256>>>((const float4*)E_X, (const uint4*)pE16,
                                                 (float4*)outE, pesum, pesq,
                                                 gamma_e, beta_e);
}